// round 1
// baseline (speedup 1.0000x reference)
#include <cuda_runtime.h>
#include <math.h>

#define NROW 16384
#define DD 64
#define BK 32
#define BM 128
#define NT (NROW / BK)

// scratch: tangent matrix T = logmap0(hyp_linear(h)), with T[:,0] = 1.0 (rowsum trick)
__device__ float g_T[(size_t)NROW * DD];

__device__ __forceinline__ unsigned long long pk2(float a, float b) {
    unsigned long long r;
    asm("mov.b64 %0, {%1,%2};" : "=l"(r) : "f"(a), "f"(b));
    return r;
}
__device__ __forceinline__ void fma2(unsigned long long& d, unsigned long long a, unsigned long long b) {
    asm("fma.rn.f32x2 %0, %1, %2, %0;" : "+l"(d) : "l"(a), "l"(b));
}

// ---------------------------------------------------------------------------
// Kernel A: per-row  T = logmap0( hyp_linear(point) ),  T[:,0] = 1.0
// If raw!=0, first maps raw x -> hyperbolic point (proj(expmap0(proj_tan0(x)))).
// One thread per row. W and the bias tangent ub live in smem.
// ---------------------------------------------------------------------------
__global__ void __launch_bounds__(256) klinear(
    const float* __restrict__ in, const float* __restrict__ W,
    const float* __restrict__ b, int raw)
{
    __shared__ float Ws[DD * DD];
    __shared__ float ub[DD];

    for (int i = threadIdx.x; i < DD * DD; i += 256) Ws[i] = W[i];
    if (threadIdx.x == 0) {
        // hyp_bias = proj(expmap0(proj_tan0(b))); ub = logmap0(hyp_bias) tail
        float bn2 = 0.f;
        for (int j = 1; j < DD; j++) bn2 += b[j] * b[j];
        float bn = fmaxf(sqrtf(bn2), 1e-15f);
        float sb = sinhf(bn) / bn;
        float h2 = 0.f;
        for (int j = 1; j < DD; j++) { float t = sb * b[j]; h2 += t * t; }
        float hb0 = sqrtf(fmaxf(1.f + h2, 1e-7f));
        float un  = fmaxf(sqrtf(h2), 1e-15f);
        float cb  = acoshf(fmaxf(hb0, 1.f + 1e-7f)) / un;
        ub[0] = 0.f;
        for (int j = 1; j < DD; j++) ub[j] = cb * (sb * b[j]);
    }
    __syncthreads();

    const int r = blockIdx.x * 256 + threadIdx.x;
    const float* row = in + (size_t)r * DD;

    float p[DD];
    float p0;
    if (raw) {
        // x_hyp = proj(expmap0(proj_tan0(x)))
        float n2 = 0.f;
#pragma unroll
        for (int j = 1; j < DD; j++) { p[j] = row[j]; n2 += p[j] * p[j]; }
        float xn = fmaxf(sqrtf(n2), 1e-15f);
        float s  = sinhf(xn) / xn;
        float t2 = 0.f;
#pragma unroll
        for (int j = 1; j < DD; j++) { p[j] = s * p[j]; t2 += p[j] * p[j]; }
        p0 = sqrtf(fmaxf(1.f + t2, 1e-7f));
    } else {
        p0 = row[0];
#pragma unroll
        for (int j = 1; j < DD; j++) p[j] = row[j];
    }

    // u = logmap0(p)   (tail only; u[0] = 0)
    float yn2 = 0.f;
#pragma unroll
    for (int j = 1; j < DD; j++) yn2 += p[j] * p[j];
    float yn = fmaxf(sqrtf(yn2), 1e-15f);
    float cl = acoshf(fmaxf(p0, 1.f + 1e-7f)) / yn;
    float u[DD];
#pragma unroll
    for (int j = 1; j < DD; j++) u[j] = cl * p[j];

    // v = u @ W^T  (tail cols only; col 0 of result discarded by expmap0, k=0 term is 0)
    float v[DD];
#pragma unroll 2
    for (int j = 1; j < DD; j++) {
        const float* wr = &Ws[j * DD];
        float a0 = 0.f, a1 = 0.f;
#pragma unroll
        for (int k = 1; k < DD; k += 2) {
            a0 = fmaf(u[k], wr[k], a0);
            if (k + 1 < DD) a1 = fmaf(u[k + 1], wr[k + 1], a1);
        }
        v[j] = a0 + a1;
    }

    // res = proj(expmap0(v))     (v becomes res tail "rt")
    float vn2 = 0.f;
#pragma unroll
    for (int j = 1; j < DD; j++) vn2 += v[j] * v[j];
    float vn = fmaxf(sqrtf(vn2), 1e-15f);
    float se = sinhf(vn) / vn;
    float rt2 = 0.f;
#pragma unroll
    for (int j = 1; j < DD; j++) { v[j] = se * v[j]; rt2 += v[j] * v[j]; }
    float r0 = sqrtf(fmaxf(1.f + rt2, 1e-7f));

    // mobius_add(res, hyp_bias):
    //   ptransp0: yhat = rt/||rt||; alpha = yhat . ub; w = ub - alpha*(1-r0)*yhat
    //   proj_tan: v2_0 = (rt . w) / max(r0, EPS)
    //   expmap(v2, res)
    float ynb = fmaxf(sqrtf(rt2), 1e-15f);
    float alpha = 0.f;
#pragma unroll
    for (int j = 1; j < DD; j++) alpha += (v[j] / ynb) * ub[j];
    float cf = alpha * (1.f - r0);
    float w[DD];
    float ux = 0.f, sw2 = 0.f;
#pragma unroll
    for (int j = 1; j < DD; j++) {
        w[j] = ub[j] - cf * (v[j] / ynb);
        ux  += v[j] * w[j];
        sw2 += w[j] * w[j];
    }
    float v20   = ux / fmaxf(r0, 1e-7f);
    float md    = sw2 - v20 * v20;                       // mink_dot(v2,v2)
    float normu = fminf(sqrtf(fmaxf(md, 1e-7f)), 1e6f);
    float theta = fmaxf(normu, 1e-15f);
    float chv   = coshf(theta);
    float scl   = sinhf(theta) / theta;
    float so2 = 0.f;
#pragma unroll
    for (int j = 1; j < DD; j++) { v[j] = chv * v[j] + scl * w[j]; so2 += v[j] * v[j]; }
    float o0 = sqrtf(fmaxf(1.f + so2, 1e-7f));          // proj

    // T row = logmap0(out);  T[:,0] = 1.0 (rowsum trick for the GEMM)
    float tn = fmaxf(sqrtf(so2), 1e-15f);
    float c3 = acoshf(fmaxf(o0, 1.f + 1e-7f)) / tn;
    float* To = g_T + (size_t)r * DD;
    To[0] = 1.0f;
#pragma unroll
    for (int j = 1; j < DD; j++) To[j] = c3 * v[j];
}

// ---------------------------------------------------------------------------
// Kernel G: Z = adj @ T (col 0 = rowsum), fused epilogue:
//   zt = rinv * Z[1:]; agg = proj(expmap0(zt)); h = proj(expmap0(relu(logmap0(agg))))
// CTA tile: 128 rows x 64 cols, 256 threads, thread tile 4 rows x 8 cols
// (16 f32x2 accumulators), BK=32, register-staged double buffering.
// ---------------------------------------------------------------------------
__global__ void __launch_bounds__(256) kagg(
    const float* __restrict__ adj, float* __restrict__ out)
{
    __shared__ float sm[BM * 66];          // mainloop: adjS[128][33] + Ts[32][64]; epilogue: z[128][66]
    float* adjS = sm;                      // 128*33 = 4224 floats
    float* Ts   = sm + BM * 33;            // 32*64  = 2048 floats

    const int tid = threadIdx.x;
    const int tx = tid & 7;                // col group (8 cols each)
    const int ty = tid >> 3;               // row group (4 rows each)
    const int rbase = blockIdx.x * BM;

    int arow[4], akq[4];
#pragma unroll
    for (int i = 0; i < 4; i++) { int f = tid + i * 256; arow[i] = f >> 3; akq[i] = f & 7; }
    int tk[2], tc[2];
#pragma unroll
    for (int i = 0; i < 2; i++) { int f = tid + i * 256; tk[i] = f >> 4; tc[i] = f & 15; }

    const float* abase[4];
#pragma unroll
    for (int i = 0; i < 4; i++)
        abase[i] = adj + (size_t)(rbase + arow[i]) * NROW + akq[i] * 4;
    const float* tbase[2];
#pragma unroll
    for (int i = 0; i < 2; i++)
        tbase[i] = g_T + (size_t)tk[i] * DD + tc[i] * 4;

    unsigned long long acc[4][4];
#pragma unroll
    for (int i = 0; i < 4; i++)
#pragma unroll
        for (int j = 0; j < 4; j++) acc[i][j] = 0ULL;

    // prologue: stage tile 0 into registers
    float4 ra[4], rT[2];
#pragma unroll
    for (int i = 0; i < 4; i++) ra[i] = *(const float4*)(abase[i]);
#pragma unroll
    for (int i = 0; i < 2; i++) rT[i] = *(const float4*)(tbase[i]);

    for (int t = 0; t < NT; t++) {
        // commit staged tile t to smem
#pragma unroll
        for (int i = 0; i < 4; i++) {
            int s = arow[i] * 33 + akq[i] * 4;
            adjS[s] = ra[i].x; adjS[s + 1] = ra[i].y; adjS[s + 2] = ra[i].z; adjS[s + 3] = ra[i].w;
        }
#pragma unroll
        for (int i = 0; i < 2; i++)
            *(float4*)&Ts[tk[i] * DD + tc[i] * 4] = rT[i];
        __syncthreads();

        // prefetch tile t+1 into registers (overlaps with compute below)
        if (t + 1 < NT) {
            const int k0 = (t + 1) * BK;
#pragma unroll
            for (int i = 0; i < 4; i++) ra[i] = *(const float4*)(abase[i] + k0);
#pragma unroll
            for (int i = 0; i < 2; i++) rT[i] = *(const float4*)(tbase[i] + (size_t)k0 * DD);
        }

        // compute tile t: 16 FFMA2 per k per thread
#pragma unroll
        for (int k = 0; k < BK; k++) {
            ulonglong2 t0 = *(const ulonglong2*)&Ts[k * DD + tx * 8];
            ulonglong2 t1 = *(const ulonglong2*)&Ts[k * DD + tx * 8 + 4];
#pragma unroll
            for (int i = 0; i < 4; i++) {
                float a = adjS[(ty * 4 + i) * 33 + k];
                unsigned long long pa = pk2(a, a);
                fma2(acc[i][0], pa, t0.x);
                fma2(acc[i][1], pa, t0.y);
                fma2(acc[i][2], pa, t1.x);
                fma2(acc[i][3], pa, t1.y);
            }
        }
        __syncthreads();
    }

    // stage Z into smem (row stride 66 -> conflict-light column reads, 8B aligned stores)
#pragma unroll
    for (int i = 0; i < 4; i++) {
        int r = ty * 4 + i;
#pragma unroll
        for (int j = 0; j < 4; j++)
            *(unsigned long long*)&sm[r * 66 + tx * 8 + j * 2] = acc[i][j];
    }
    __syncthreads();

    // epilogue: one thread per row
    if (tid < BM) {
        float z[DD];
#pragma unroll
        for (int j = 0; j < DD; j++) z[j] = sm[tid * 66 + j];

        float s0 = z[0];                                  // rowsum (T[:,0]==1)
        float rinv = (s0 != 0.f) ? (1.f / s0) : 0.f;
        float zn2 = 0.f;
#pragma unroll
        for (int j = 1; j < DD; j++) { z[j] = rinv * z[j]; zn2 += z[j] * z[j]; }
        // agg = proj(expmap0(zt))
        float xn = fmaxf(sqrtf(zn2), 1e-15f);
        float sg = sinhf(xn) / xn;
        float a2 = 0.f;
#pragma unroll
        for (int j = 1; j < DD; j++) { z[j] = sg * z[j]; a2 += z[j] * z[j]; }
        float a0 = sqrtf(fmaxf(1.f + a2, 1e-7f));
        // hyp_act: relu(logmap0(agg)) -> expmap0 -> proj
        float ynA = fmaxf(sqrtf(a2), 1e-15f);
        float clA = acoshf(fmaxf(a0, 1.f + 1e-7f)) / ynA;
        float rn2 = 0.f;
#pragma unroll
        for (int j = 1; j < DD; j++) { z[j] = fmaxf(clA * z[j], 0.f); rn2 += z[j] * z[j]; }
        float rn = fmaxf(sqrtf(rn2), 1e-15f);
        float sh = sinhf(rn) / rn;
        float h2s = 0.f;
#pragma unroll
        for (int j = 1; j < DD; j++) { z[j] = sh * z[j]; h2s += z[j] * z[j]; }
        float h0 = sqrtf(fmaxf(1.f + h2s, 1e-7f));

        float* orow = out + (size_t)(rbase + tid) * DD;
        orow[0] = h0;
#pragma unroll
        for (int j = 1; j < DD; j++) orow[j] = z[j];
    }
}

// ---------------------------------------------------------------------------
extern "C" void kernel_launch(void* const* d_in, const int* in_sizes, int n_in,
                              void* d_out, int out_size) {
    (void)in_sizes; (void)n_in; (void)out_size;
    const float* x   = (const float*)d_in[0];
    const float* adj = (const float*)d_in[1];
    const float* W1  = (const float*)d_in[2];
    const float* b1  = (const float*)d_in[3];
    const float* W2  = (const float*)d_in[4];
    const float* b2  = (const float*)d_in[5];

    float* out = (float*)d_out;
    float* h1 = out;
    float* h2 = out + (size_t)NROW * DD;

    // layer 1
    klinear<<<NROW / 256, 256>>>(x, W1, b1, 1);
    kagg<<<NROW / BM, 256>>>(adj, h1);
    // layer 2
    klinear<<<NROW / 256, 256>>>(h1, W2, b2, 0);
    kagg<<<NROW / BM, 256>>>(adj, h2);
}

// round 9
// speedup vs baseline: 2.2484x; 2.2484x over previous
#include <cuda_runtime.h>
#include <math.h>
#include <cstdint>
#include <mma.h>

using namespace nvcuda;

#define NROW 16384
#define DD 64
#define BM 128
#define BN 64
#define BK 32
#define NT (NROW / BK)              // 512 k-chunks
#define STAGES 4
#define LDA 40                      // A tile row stride (floats), padded
#define LDB 72                      // B tile row stride (floats), padded
#define LDE 68                      // epilogue stage stride (floats)
#define A_BYTES (BM * LDA * 4)      // 20480
#define B_BYTES (BK * LDB * 4)      // 9216
#define STAGE_BYTES (A_BYTES + B_BYTES)   // 29696
#define SMEM_TOTAL (STAGES * STAGE_BYTES) // 118784

// scratch: T = logmap0(hyp_linear(h)), row-major [16384][64], col 0 = 1.0 (rowsum trick)
__device__ __align__(256) float g_T[(size_t)NROW * DD];

__device__ __forceinline__ void cp16(uint32_t dst, const void* src) {
    asm volatile("cp.async.cg.shared.global [%0], [%1], 16;" :: "r"(dst), "l"(src));
}
#define CP_COMMIT() asm volatile("cp.async.commit_group;" ::: "memory")
#define CP_WAIT3()  asm volatile("cp.async.wait_group 3;" ::: "memory")
#define CP_WAIT0()  asm volatile("cp.async.wait_group 0;" ::: "memory")

__device__ __forceinline__ uint32_t smem_u32(const void* p) {
    uint32_t a;
    asm("{ .reg .u64 t; cvta.to.shared.u64 t, %1; cvt.u32.u64 %0, t; }" : "=r"(a) : "l"(p));
    return a;
}

// ---------------------------------------------------------------------------
// Kernel A: per-row T[r][:] = logmap0( hyp_linear(point) ),  T[r][0] = 1.0
// ---------------------------------------------------------------------------
__global__ void __launch_bounds__(256) klinear(
    const float* __restrict__ in, const float* __restrict__ W,
    const float* __restrict__ b, int raw)
{
    __shared__ float Ws[DD * DD];
    __shared__ float ub[DD];

    for (int i = threadIdx.x; i < DD * DD; i += 256) Ws[i] = W[i];
    if (threadIdx.x == 0) {
        float bn2 = 0.f;
        for (int j = 1; j < DD; j++) bn2 += b[j] * b[j];
        float bn = fmaxf(sqrtf(bn2), 1e-15f);
        float sb = sinhf(bn) / bn;
        float h2 = 0.f;
        for (int j = 1; j < DD; j++) { float t = sb * b[j]; h2 += t * t; }
        float hb0 = sqrtf(fmaxf(1.f + h2, 1e-7f));
        float un  = fmaxf(sqrtf(h2), 1e-15f);
        float cb  = acoshf(fmaxf(hb0, 1.f + 1e-7f)) / un;
        ub[0] = 0.f;
        for (int j = 1; j < DD; j++) ub[j] = cb * (sb * b[j]);
    }
    __syncthreads();

    const int r = blockIdx.x * 256 + threadIdx.x;
    const float* row = in + (size_t)r * DD;

    float p[DD]; float p0;
    if (raw) {
        float n2 = 0.f;
#pragma unroll
        for (int j = 1; j < DD; j++) { p[j] = row[j]; n2 += p[j] * p[j]; }
        float xn = fmaxf(sqrtf(n2), 1e-15f);
        float s  = sinhf(xn) / xn;
        float t2 = 0.f;
#pragma unroll
        for (int j = 1; j < DD; j++) { p[j] = s * p[j]; t2 += p[j] * p[j]; }
        p0 = sqrtf(fmaxf(1.f + t2, 1e-7f));
    } else {
        p0 = row[0];
#pragma unroll
        for (int j = 1; j < DD; j++) p[j] = row[j];
    }

    // u = logmap0(p) tail
    float yn2 = 0.f;
#pragma unroll
    for (int j = 1; j < DD; j++) yn2 += p[j] * p[j];
    float yn = fmaxf(sqrtf(yn2), 1e-15f);
    float cl = acoshf(fmaxf(p0, 1.f + 1e-7f)) / yn;
    float u[DD];
#pragma unroll
    for (int j = 1; j < DD; j++) u[j] = cl * p[j];

    // v = u @ W^T (tail)
    float v[DD];
#pragma unroll 2
    for (int j = 1; j < DD; j++) {
        const float* wr = &Ws[j * DD];
        float a0 = 0.f, a1 = 0.f;
#pragma unroll
        for (int k = 1; k < DD; k += 2) {
            a0 = fmaf(u[k], wr[k], a0);
            if (k + 1 < DD) a1 = fmaf(u[k + 1], wr[k + 1], a1);
        }
        v[j] = a0 + a1;
    }

    // res = proj(expmap0(v))
    float vn2 = 0.f;
#pragma unroll
    for (int j = 1; j < DD; j++) vn2 += v[j] * v[j];
    float vn = fmaxf(sqrtf(vn2), 1e-15f);
    float se = sinhf(vn) / vn;
    float rt2 = 0.f;
#pragma unroll
    for (int j = 1; j < DD; j++) { v[j] = se * v[j]; rt2 += v[j] * v[j]; }
    float r0 = sqrtf(fmaxf(1.f + rt2, 1e-7f));

    // mobius_add(res, hyp_bias)
    float ynb = fmaxf(sqrtf(rt2), 1e-15f);
    float alpha = 0.f;
#pragma unroll
    for (int j = 1; j < DD; j++) alpha += (v[j] / ynb) * ub[j];
    float cf = alpha * (1.f - r0);
    float w[DD];
    float ux = 0.f, sw2 = 0.f;
#pragma unroll
    for (int j = 1; j < DD; j++) {
        w[j] = ub[j] - cf * (v[j] / ynb);
        ux  += v[j] * w[j];
        sw2 += w[j] * w[j];
    }
    float v20   = ux / fmaxf(r0, 1e-7f);
    float md    = sw2 - v20 * v20;
    float normu = fminf(sqrtf(fmaxf(md, 1e-7f)), 1e6f);
    float theta = fmaxf(normu, 1e-15f);
    float chv   = coshf(theta);
    float scl   = sinhf(theta) / theta;
    float so2 = 0.f;
#pragma unroll
    for (int j = 1; j < DD; j++) { v[j] = chv * v[j] + scl * w[j]; so2 += v[j] * v[j]; }
    float o0 = sqrtf(fmaxf(1.f + so2, 1e-7f));

    // T row = logmap0(out);  T[r][0] = 1.0
    float tn = fmaxf(sqrtf(so2), 1e-15f);
    float c3 = acoshf(fmaxf(o0, 1.f + 1e-7f)) / tn;
    float* To = g_T + (size_t)r * DD;
    To[0] = 1.0f;
#pragma unroll
    for (int j = 1; j < DD; j++) To[j] = c3 * v[j];
}

// ---------------------------------------------------------------------------
// Kernel G: Z = adj_tile(128 x 16384) @ T (16384 x 64) via tf32 WMMA,
// 4-stage cp.async pipeline, fused hyperbolic epilogue. Z[:,0] = rowsum.
// ---------------------------------------------------------------------------
__global__ void __launch_bounds__(256) kagg(
    const float* __restrict__ adj, float* __restrict__ out)
{
    extern __shared__ char smem[];
    const uint32_t sbase = smem_u32(smem);
    const int tid = threadIdx.x;
    const int wid = tid >> 5;
    const int lid = tid & 31;
    const int wr = wid & 3;          // warp row group (32 rows)
    const int wc = wid >> 2;         // warp col group (32 cols)
    const int rbase = blockIdx.x * BM;

    // per-thread 6 cp.async chunks per stage
    uint32_t soff[6];
    const float* gp[6];
    int step[6];
#pragma unroll
    for (int i = 0; i < 6; i++) {
        int c = tid + i * 256;
        if (c < 1024) {                            // A: 128 rows x 8 chunks of 16B
            int row = c >> 3, q = c & 7;
            soff[i] = row * (LDA * 4) + q * 16;
            gp[i]   = adj + (size_t)(rbase + row) * NROW + q * 4;
            step[i] = BK;                          // floats per k-chunk
        } else {                                   // B: 32 rows x 16 chunks of 16B
            int c2 = c - 1024;
            int k = c2 >> 4, q = c2 & 15;
            soff[i] = A_BYTES + k * (LDB * 4) + q * 16;
            gp[i]   = g_T + (size_t)k * DD + q * 4;
            step[i] = BK * DD;                     // 2048 floats per k-chunk
        }
    }

    // prologue: fill all stages
#pragma unroll
    for (int t = 0; t < STAGES; t++) {
        uint32_t sb = sbase + t * STAGE_BYTES;
#pragma unroll
        for (int i = 0; i < 6; i++) cp16(sb + soff[i], gp[i] + (size_t)t * step[i]);
        CP_COMMIT();
    }

    wmma::fragment<wmma::accumulator, 16, 16, 8, float> acc[2][2];
#pragma unroll
    for (int i = 0; i < 2; i++)
#pragma unroll
        for (int j = 0; j < 2; j++) wmma::fill_fragment(acc[i][j], 0.0f);

    for (int t = 0; t < NT; t++) {
        const int s = t % STAGES;
        CP_WAIT3();
        __syncthreads();

        const float* As = (const float*)(smem + s * STAGE_BYTES);
        const float* Bs = (const float*)(smem + s * STAGE_BYTES + A_BYTES);

#pragma unroll
        for (int kk = 0; kk < BK / 8; kk++) {
            wmma::fragment<wmma::matrix_a, 16, 16, 8, wmma::precision::tf32, wmma::row_major> a0, a1;
            wmma::fragment<wmma::matrix_b, 16, 16, 8, wmma::precision::tf32, wmma::row_major> b0, b1;
            wmma::load_matrix_sync(a0, As + (wr * 32) * LDA + kk * 8, LDA);
            wmma::load_matrix_sync(a1, As + (wr * 32 + 16) * LDA + kk * 8, LDA);
            wmma::load_matrix_sync(b0, Bs + (kk * 8) * LDB + wc * 32, LDB);
            wmma::load_matrix_sync(b1, Bs + (kk * 8) * LDB + wc * 32 + 16, LDB);
#pragma unroll
            for (int e = 0; e < a0.num_elements; e++) {
                a0.x[e] = wmma::__float_to_tf32(a0.x[e]);
                a1.x[e] = wmma::__float_to_tf32(a1.x[e]);
            }
#pragma unroll
            for (int e = 0; e < b0.num_elements; e++) {
                b0.x[e] = wmma::__float_to_tf32(b0.x[e]);
                b1.x[e] = wmma::__float_to_tf32(b1.x[e]);
            }
            wmma::mma_sync(acc[0][0], a0, b0, acc[0][0]);
            wmma::mma_sync(acc[0][1], a0, b1, acc[0][1]);
            wmma::mma_sync(acc[1][0], a1, b0, acc[1][0]);
            wmma::mma_sync(acc[1][1], a1, b1, acc[1][1]);
        }
        __syncthreads();

        if (t + STAGES < NT) {
            uint32_t sb = sbase + s * STAGE_BYTES;
#pragma unroll
            for (int i = 0; i < 6; i++) cp16(sb + soff[i], gp[i] + (size_t)(t + STAGES) * step[i]);
        }
        CP_COMMIT();   // empty group in the tail keeps wait_group accounting aligned
    }
    CP_WAIT0();
    __syncthreads();

    // stage Z into smem (row stride LDE)
    float* E = (float*)smem;
#pragma unroll
    for (int i = 0; i < 2; i++)
#pragma unroll
        for (int j = 0; j < 2; j++)
            wmma::store_matrix_sync(&E[(wr * 32 + i * 16) * LDE + wc * 32 + j * 16],
                                    acc[i][j], LDE, wmma::mem_row_major);
    __syncthreads();

    // epilogue: one thread per row
    if (tid < BM) {
        float z[DD];
#pragma unroll
        for (int j = 0; j < DD; j++) z[j] = E[tid * LDE + j];

        float s0 = z[0];                              // rowsum (T col 0 == 1)
        float rinv = (s0 != 0.f) ? (1.f / s0) : 0.f;
        float zn2 = 0.f;
#pragma unroll
        for (int j = 1; j < DD; j++) { z[j] = rinv * z[j]; zn2 += z[j] * z[j]; }
        // agg = proj(expmap0(zt))
        float xn = fmaxf(sqrtf(zn2), 1e-15f);
        float sg = sinhf(xn) / xn;
        float a2 = 0.f;
#pragma unroll
        for (int j = 1; j < DD; j++) { z[j] = sg * z[j]; a2 += z[j] * z[j]; }
        float a0 = sqrtf(fmaxf(1.f + a2, 1e-7f));
        // hyp_act: relu(logmap0(agg)) -> expmap0 -> proj
        float ynA = fmaxf(sqrtf(a2), 1e-15f);
        float clA = acoshf(fmaxf(a0, 1.f + 1e-7f)) / ynA;
        float rn2 = 0.f;
#pragma unroll
        for (int j = 1; j < DD; j++) { z[j] = fmaxf(clA * z[j], 0.f); rn2 += z[j] * z[j]; }
        float rn = fmaxf(sqrtf(rn2), 1e-15f);
        float sh = sinhf(rn) / rn;
        float h2s = 0.f;
#pragma unroll
        for (int j = 1; j < DD; j++) { z[j] = sh * z[j]; h2s += z[j] * z[j]; }
        float h0 = sqrtf(fmaxf(1.f + h2s, 1e-7f));

        float* orow = out + (size_t)(rbase + tid) * DD;
        orow[0] = h0;
#pragma unroll
        for (int j = 1; j < DD; j++) orow[j] = z[j];
    }
}

// ---------------------------------------------------------------------------
extern "C" void kernel_launch(void* const* d_in, const int* in_sizes, int n_in,
                              void* d_out, int out_size) {
    (void)in_sizes; (void)n_in; (void)out_size;
    const float* x   = (const float*)d_in[0];
    const float* adj = (const float*)d_in[1];
    const float* W1  = (const float*)d_in[2];
    const float* b1  = (const float*)d_in[3];
    const float* W2  = (const float*)d_in[4];
    const float* b2  = (const float*)d_in[5];

    float* out = (float*)d_out;
    float* h1 = out;
    float* h2 = out + (size_t)NROW * DD;

    cudaFuncSetAttribute(kagg, cudaFuncAttributeMaxDynamicSharedMemorySize, SMEM_TOTAL);

    klinear<<<NROW / 256, 256>>>(x, W1, b1, 1);
    kagg<<<NROW / BM, 256, SMEM_TOTAL>>>(adj, h1);
    klinear<<<NROW / 256, 256>>>(h1, W2, b2, 0);
    kagg<<<NROW / BM, 256, SMEM_TOTAL>>>(adj, h2);
}

// round 13
// speedup vs baseline: 2.5151x; 1.1186x over previous
#include <cuda_runtime.h>
#include <math.h>
#include <cstdint>
#include <mma.h>

using namespace nvcuda;

#define NROW 16384
#define DD 64
#define BM 64
#define BK 32
#define NT (NROW / BK)              // 512 k-chunks
#define STAGES 4
#define LDA 40                      // A tile row stride (floats), padded
#define LDB 72                      // B tile row stride (floats), padded
#define LDE 68                      // epilogue stage stride (floats)
#define A_BYTES (BM * LDA * 4)      // 10240
#define B_BYTES (BK * LDB * 4)      // 9216
#define STAGE_BYTES (A_BYTES + B_BYTES)   // 19456
#define SMEM_TOTAL (STAGES * STAGE_BYTES) // 77824  -> 2 CTAs/SM

// scratch: T = logmap0(hyp_linear(h)), row-major [16384][64], col 0 = 1.0 (rowsum trick)
__device__ __align__(256) float g_T[(size_t)NROW * DD];

__device__ __forceinline__ void cp16(uint32_t dst, const void* src) {
    asm volatile("cp.async.cg.shared.global [%0], [%1], 16;" :: "r"(dst), "l"(src));
}
#define CP_COMMIT() asm volatile("cp.async.commit_group;" ::: "memory")
#define CP_WAIT3()  asm volatile("cp.async.wait_group 3;" ::: "memory")
#define CP_WAIT0()  asm volatile("cp.async.wait_group 0;" ::: "memory")

__device__ __forceinline__ uint32_t smem_u32(const void* p) {
    uint32_t a;
    asm("{ .reg .u64 t; cvta.to.shared.u64 t, %1; cvt.u32.u64 %0, t; }" : "=r"(a) : "l"(p));
    return a;
}

// ---------------------------------------------------------------------------
// Kernel A: per-row T[r][:] = logmap0( hyp_linear(point) ),  T[r][0] = 1.0
// ---------------------------------------------------------------------------
__global__ void __launch_bounds__(256) klinear(
    const float* __restrict__ in, const float* __restrict__ W,
    const float* __restrict__ b, int raw)
{
    __shared__ float Ws[DD * DD];
    __shared__ float ub[DD];

    for (int i = threadIdx.x; i < DD * DD; i += 256) Ws[i] = W[i];
    if (threadIdx.x == 0) {
        float bn2 = 0.f;
        for (int j = 1; j < DD; j++) bn2 += b[j] * b[j];
        float bn = fmaxf(sqrtf(bn2), 1e-15f);
        float sb = sinhf(bn) / bn;
        float h2 = 0.f;
        for (int j = 1; j < DD; j++) { float t = sb * b[j]; h2 += t * t; }
        float hb0 = sqrtf(fmaxf(1.f + h2, 1e-7f));
        float un  = fmaxf(sqrtf(h2), 1e-15f);
        float cb  = acoshf(fmaxf(hb0, 1.f + 1e-7f)) / un;
        ub[0] = 0.f;
        for (int j = 1; j < DD; j++) ub[j] = cb * (sb * b[j]);
    }
    __syncthreads();

    const int r = blockIdx.x * 256 + threadIdx.x;
    const float* row = in + (size_t)r * DD;

    float p[DD]; float p0;
    if (raw) {
        float n2 = 0.f;
#pragma unroll
        for (int j = 1; j < DD; j++) { p[j] = row[j]; n2 += p[j] * p[j]; }
        float xn = fmaxf(sqrtf(n2), 1e-15f);
        float s  = sinhf(xn) / xn;
        float t2 = 0.f;
#pragma unroll
        for (int j = 1; j < DD; j++) { p[j] = s * p[j]; t2 += p[j] * p[j]; }
        p0 = sqrtf(fmaxf(1.f + t2, 1e-7f));
    } else {
        p0 = row[0];
#pragma unroll
        for (int j = 1; j < DD; j++) p[j] = row[j];
    }

    // u = logmap0(p) tail
    float yn2 = 0.f;
#pragma unroll
    for (int j = 1; j < DD; j++) yn2 += p[j] * p[j];
    float yn = fmaxf(sqrtf(yn2), 1e-15f);
    float cl = acoshf(fmaxf(p0, 1.f + 1e-7f)) / yn;
    float u[DD];
#pragma unroll
    for (int j = 1; j < DD; j++) u[j] = cl * p[j];

    // v = u @ W^T (tail)
    float v[DD];
#pragma unroll 2
    for (int j = 1; j < DD; j++) {
        const float* wr = &Ws[j * DD];
        float a0 = 0.f, a1 = 0.f;
#pragma unroll
        for (int k = 1; k < DD; k += 2) {
            a0 = fmaf(u[k], wr[k], a0);
            if (k + 1 < DD) a1 = fmaf(u[k + 1], wr[k + 1], a1);
        }
        v[j] = a0 + a1;
    }

    // res = proj(expmap0(v))
    float vn2 = 0.f;
#pragma unroll
    for (int j = 1; j < DD; j++) vn2 += v[j] * v[j];
    float vn = fmaxf(sqrtf(vn2), 1e-15f);
    float se = sinhf(vn) / vn;
    float rt2 = 0.f;
#pragma unroll
    for (int j = 1; j < DD; j++) { v[j] = se * v[j]; rt2 += v[j] * v[j]; }
    float r0 = sqrtf(fmaxf(1.f + rt2, 1e-7f));

    // mobius_add(res, hyp_bias)
    float ynb = fmaxf(sqrtf(rt2), 1e-15f);
    float alpha = 0.f;
#pragma unroll
    for (int j = 1; j < DD; j++) alpha += (v[j] / ynb) * ub[j];
    float cf = alpha * (1.f - r0);
    float w[DD];
    float ux = 0.f, sw2 = 0.f;
#pragma unroll
    for (int j = 1; j < DD; j++) {
        w[j] = ub[j] - cf * (v[j] / ynb);
        ux  += v[j] * w[j];
        sw2 += w[j] * w[j];
    }
    float v20   = ux / fmaxf(r0, 1e-7f);
    float md    = sw2 - v20 * v20;
    float normu = fminf(sqrtf(fmaxf(md, 1e-7f)), 1e6f);
    float theta = fmaxf(normu, 1e-15f);
    float chv   = coshf(theta);
    float scl   = sinhf(theta) / theta;
    float so2 = 0.f;
#pragma unroll
    for (int j = 1; j < DD; j++) { v[j] = chv * v[j] + scl * w[j]; so2 += v[j] * v[j]; }
    float o0 = sqrtf(fmaxf(1.f + so2, 1e-7f));

    // T row = logmap0(out);  T[r][0] = 1.0
    float tn = fmaxf(sqrtf(so2), 1e-15f);
    float c3 = acoshf(fmaxf(o0, 1.f + 1e-7f)) / tn;
    float* To = g_T + (size_t)r * DD;
    To[0] = 1.0f;
#pragma unroll
    for (int j = 1; j < DD; j++) To[j] = c3 * v[j];
}

// ---------------------------------------------------------------------------
// Kernel G: Z = adj_tile(64 x 16384) @ T (16384 x 64) via tf32 WMMA,
// 4-stage cp.async pipeline, 2 CTAs/SM, fused hyperbolic epilogue.
// Z[:,0] = rowsum (T col 0 == 1). No explicit tf32 cvt (HW truncates).
// ---------------------------------------------------------------------------
__global__ void __launch_bounds__(256, 2) kagg(
    const float* __restrict__ adj, float* __restrict__ out)
{
    extern __shared__ char smem[];
    const uint32_t sbase = smem_u32(smem);
    const int tid = threadIdx.x;
    const int wid = tid >> 5;
    const int wr = wid & 3;          // warp row group (16 rows each)
    const int wc = wid >> 2;         // warp col group (32 cols each)
    const int rbase = blockIdx.x * BM;

    // per-thread 4 cp.async chunks per stage (1024 x 16B)
    uint32_t soff[4];
    const float* gp[4];
    int step[4];
#pragma unroll
    for (int i = 0; i < 4; i++) {
        int c = tid + i * 256;
        if (c < 512) {                             // A: 64 rows x 8 chunks of 16B
            int row = c >> 3, q = c & 7;
            soff[i] = row * (LDA * 4) + q * 16;
            gp[i]   = adj + (size_t)(rbase + row) * NROW + q * 4;
            step[i] = BK;
        } else {                                   // B: 32 rows x 16 chunks of 16B
            int c2 = c - 512;
            int k = c2 >> 4, q = c2 & 15;
            soff[i] = A_BYTES + k * (LDB * 4) + q * 16;
            gp[i]   = g_T + (size_t)k * DD + q * 4;
            step[i] = BK * DD;
        }
    }

    // prologue: fill all stages
#pragma unroll
    for (int t = 0; t < STAGES; t++) {
        uint32_t sb = sbase + t * STAGE_BYTES;
#pragma unroll
        for (int i = 0; i < 4; i++) cp16(sb + soff[i], gp[i] + (size_t)t * step[i]);
        CP_COMMIT();
    }

    wmma::fragment<wmma::accumulator, 16, 16, 8, float> acc[2];
#pragma unroll
    for (int j = 0; j < 2; j++) wmma::fill_fragment(acc[j], 0.0f);

    for (int t = 0; t < NT; t++) {
        const int s = t % STAGES;
        CP_WAIT3();
        __syncthreads();

        const float* As = (const float*)(smem + s * STAGE_BYTES);
        const float* Bs = (const float*)(smem + s * STAGE_BYTES + A_BYTES);

#pragma unroll
        for (int kk = 0; kk < BK / 8; kk++) {
            wmma::fragment<wmma::matrix_a, 16, 16, 8, wmma::precision::tf32, wmma::row_major> a0;
            wmma::fragment<wmma::matrix_b, 16, 16, 8, wmma::precision::tf32, wmma::row_major> b0, b1;
            wmma::load_matrix_sync(a0, As + (wr * 16) * LDA + kk * 8, LDA);
            wmma::load_matrix_sync(b0, Bs + (kk * 8) * LDB + wc * 32, LDB);
            wmma::load_matrix_sync(b1, Bs + (kk * 8) * LDB + wc * 32 + 16, LDB);
            wmma::mma_sync(acc[0], a0, b0, acc[0]);
            wmma::mma_sync(acc[1], a0, b1, acc[1]);
        }
        __syncthreads();

        if (t + STAGES < NT) {
            uint32_t sb = sbase + s * STAGE_BYTES;
#pragma unroll
            for (int i = 0; i < 4; i++) cp16(sb + soff[i], gp[i] + (size_t)(t + STAGES) * step[i]);
        }
        CP_COMMIT();   // empty group in the tail keeps wait_group accounting aligned
    }
    CP_WAIT0();
    __syncthreads();

    // stage Z into smem (row stride LDE)
    float* E = (float*)smem;
#pragma unroll
    for (int j = 0; j < 2; j++)
        wmma::store_matrix_sync(&E[(wr * 16) * LDE + wc * 32 + j * 16],
                                acc[j], LDE, wmma::mem_row_major);
    __syncthreads();

    // epilogue: one thread per row
    if (tid < BM) {
        float z[DD];
#pragma unroll
        for (int j = 0; j < DD; j++) z[j] = E[tid * LDE + j];

        float s0 = z[0];                              // rowsum (T col 0 == 1)
        float rinv = (s0 != 0.f) ? (1.f / s0) : 0.f;
        float zn2 = 0.f;
#pragma unroll
        for (int j = 1; j < DD; j++) { z[j] = rinv * z[j]; zn2 += z[j] * z[j]; }
        // agg = proj(expmap0(zt))
        float xn = fmaxf(sqrtf(zn2), 1e-15f);
        float sg = sinhf(xn) / xn;
        float a2 = 0.f;
#pragma unroll
        for (int j = 1; j < DD; j++) { z[j] = sg * z[j]; a2 += z[j] * z[j]; }
        float a0 = sqrtf(fmaxf(1.f + a2, 1e-7f));
        // hyp_act: relu(logmap0(agg)) -> expmap0 -> proj
        float ynA = fmaxf(sqrtf(a2), 1e-15f);
        float clA = acoshf(fmaxf(a0, 1.f + 1e-7f)) / ynA;
        float rn2 = 0.f;
#pragma unroll
        for (int j = 1; j < DD; j++) { z[j] = fmaxf(clA * z[j], 0.f); rn2 += z[j] * z[j]; }
        float rn = fmaxf(sqrtf(rn2), 1e-15f);
        float sh = sinhf(rn) / rn;
        float h2s = 0.f;
#pragma unroll
        for (int j = 1; j < DD; j++) { z[j] = sh * z[j]; h2s += z[j] * z[j]; }
        float h0 = sqrtf(fmaxf(1.f + h2s, 1e-7f));

        float* orow = out + (size_t)(rbase + tid) * DD;
        orow[0] = h0;
#pragma unroll
        for (int j = 1; j < DD; j++) orow[j] = z[j];
    }
}

// ---------------------------------------------------------------------------
extern "C" void kernel_launch(void* const* d_in, const int* in_sizes, int n_in,
                              void* d_out, int out_size) {
    (void)in_sizes; (void)n_in; (void)out_size;
    const float* x   = (const float*)d_in[0];
    const float* adj = (const float*)d_in[1];
    const float* W1  = (const float*)d_in[2];
    const float* b1  = (const float*)d_in[3];
    const float* W2  = (const float*)d_in[4];
    const float* b2  = (const float*)d_in[5];

    float* out = (float*)d_out;
    float* h1 = out;
    float* h2 = out + (size_t)NROW * DD;

    cudaFuncSetAttribute(kagg, cudaFuncAttributeMaxDynamicSharedMemorySize, SMEM_TOTAL);

    klinear<<<NROW / 256, 256>>>(x, W1, b1, 1);
    kagg<<<NROW / BM, 256, SMEM_TOTAL>>>(adj, h1);
    klinear<<<NROW / 256, 256>>>(h1, W2, b2, 0);
    kagg<<<NROW / BM, 256, SMEM_TOTAL>>>(adj, h2);
}